// round 15
// baseline (speedup 1.0000x reference)
#include <cuda_runtime.h>
#include <cuda_bf16.h>
#include <cstdint>

#define BB    256
#define NE    1024
#define NTOT  2048
#define DD    256
#define STEPS 200
#define LASTN 50

// step kernel geometry
#define KS     64            // K-slab
#define NSLAB  (NTOT / KS)   // 32
#define NSTG   3             // pipeline stages
#define PITCHB 144           // bytes per smem row (64 bf16 = 128B + 16B pad)
#define STAGE_BYTES (64 * PITCHB)                   // 9216B per matrix-stage
#define SMEM_TOTAL  (4 * NSTG * STAGE_BYTES)        // 110592B

// ---------------- device scratch ----------------
__device__ __nv_bfloat16 g_Whi[NTOT * NTOT];
__device__ __nv_bfloat16 g_Wlo[NTOT * NTOT];
__device__ float g_Iff[BB * NTOT];
__device__ float g_r[2][BB * NTOT];
__device__ __nv_bfloat16 g_rhi[2][BB * NTOT];
__device__ __nv_bfloat16 g_rlo[2][BB * NTOT];
__device__ float g_acc[BB * NTOT];

// ---------------- weight prep (proven) ----------------
__global__ void prep_w_kernel(const float* __restrict__ WEE,
                              const float* __restrict__ WEI,
                              const float* __restrict__ WIE,
                              const float* __restrict__ WII) {
    __shared__ float red[256];
    int j = blockIdx.x;
    int tid = threadIdx.x;
    bool isE = (j < NE);
    const float* rawA;
    const float* rawB;
    float SA, SB;
    if (isE) {
        rawA = WEE + (size_t)j * NE;  SA = 3.75f;
        rawB = WEI + (size_t)j * NE;  SB = 1.86f;
    } else {
        int j2 = j - NE;
        rawA = WIE + (size_t)j2 * NE; SA = 3.13f;
        rawB = WII + (size_t)j2 * NE; SB = 1.11f - 0.02f;
    }
    float sA = 0.f, sB = 0.f;
    for (int k = tid; k < NE; k += 256) { sA += rawA[k]; sB += rawB[k]; }
    red[tid] = sA; __syncthreads();
    for (int s = 128; s > 0; s >>= 1) { if (tid < s) red[tid] += red[tid + s]; __syncthreads(); }
    float sumA = red[0]; __syncthreads();
    red[tid] = sB; __syncthreads();
    for (int s = 128; s > 0; s >>= 1) { if (tid < s) red[tid] += red[tid + s]; __syncthreads(); }
    float sumB = red[0];

    float gA = SA / (sumA + 1e-12f);
    float gB = SB / (sumB + 1e-12f);

    for (int k = tid; k < NE; k += 256) {
        float a = rawA[k];
        if (isE) a = fminf(a, 0.15f);
        a *= gA;
        __nv_bfloat16 ha = __float2bfloat16_rn(a);
        g_Whi[j * NTOT + k] = ha;
        g_Wlo[j * NTOT + k] = __float2bfloat16_rn(a - __bfloat162float(ha));

        float b = rawB[k];
        if (isE) b = fmaxf(b, 0.0005f);
        b = -b * gB;
        __nv_bfloat16 hb = __float2bfloat16_rn(b);
        g_Whi[j * NTOT + NE + k] = hb;
        g_Wlo[j * NTOT + NE + k] = __float2bfloat16_rn(b - __bfloat162float(hb));
    }
}

// ---------------- feed-forward currents ----------------
__global__ void iff_kernel(const float* __restrict__ x,
                           const float* __restrict__ WffE,
                           const float* __restrict__ WffI) {
    __shared__ float sx[16][DD];
    int tid = threadIdx.x;
    int jblk = blockIdx.x * 256;
    int bblk = blockIdx.y * 16;
    for (int i = 0; i < 16; i++) sx[i][tid] = x[(bblk + i) * DD + tid];
    __syncthreads();
    int j = jblk + tid;
    const float* wr = (j < NE) ? (WffE + (size_t)j * DD) : (WffI + (size_t)(j - NE) * DD);
    float acc[16];
#pragma unroll
    for (int b = 0; b < 16; b++) acc[b] = 0.f;
    for (int d = 0; d < DD; d++) {
        float wv = __ldg(wr + d);
#pragma unroll
        for (int b = 0; b < 16; b++) acc[b] += sx[b][d] * wv;
    }
    for (int b = 0; b < 16; b++) g_Iff[(bblk + b) * NTOT + j] = acc[b];
}

// ---------------- zero init ----------------
__global__ void zero_kernel() {
    int i = blockIdx.x * blockDim.x + threadIdx.x;
    int stride = gridDim.x * blockDim.x;
    const __nv_bfloat16 z16 = __float2bfloat16_rn(0.f);
    for (int k = i; k < BB * NTOT; k += stride) {
        g_r[0][k] = 0.f;  g_r[1][k] = 0.f;
        g_rhi[0][k] = z16; g_rhi[1][k] = z16;
        g_rlo[0][k] = z16; g_rlo[1][k] = z16;
        g_acc[k] = 0.f;
    }
}

// ---------------- helpers ----------------
__device__ __forceinline__ void mma_bf16(float* c, const uint32_t* a, const uint32_t* b) {
    asm volatile(
        "mma.sync.aligned.m16n8k16.row.col.f32.bf16.bf16.f32 "
        "{%0,%1,%2,%3}, {%4,%5,%6,%7}, {%8,%9}, {%0,%1,%2,%3};\n"
        : "+f"(c[0]), "+f"(c[1]), "+f"(c[2]), "+f"(c[3])
        : "r"(a[0]), "r"(a[1]), "r"(a[2]), "r"(a[3]), "r"(b[0]), "r"(b[1]));
}

__device__ __forceinline__ void ldsm4(uint32_t* r, uint32_t addr) {
    asm volatile("ldmatrix.sync.aligned.m8n8.x4.shared.b16 {%0,%1,%2,%3}, [%4];\n"
                 : "=r"(r[0]), "=r"(r[1]), "=r"(r[2]), "=r"(r[3]) : "r"(addr));
}

__device__ __forceinline__ void cpa16(uint32_t saddr, const void* gaddr) {
    asm volatile("cp.async.cg.shared.global [%0], [%1], 16;\n" :: "r"(saddr), "l"(gaddr));
}
__device__ __forceinline__ void cpa_commit() {
    asm volatile("cp.async.commit_group;\n" ::: "memory");
}
template <int N>
__device__ __forceinline__ void cpa_wait() {
    asm volatile("cp.async.wait_group %0;\n" :: "n"(N) : "memory");
}

// ---------------- one dynamics step ----------------
// CTA tile 64(M) x 64(N), 256 threads = 8 warps (2M x 4N), warp tile 32x16.
// K-slab 64, 3-stage cp.async pipeline. Per-slab order (race-free):
//   cpa_wait<1>  -> slab ks complete (per-thread)
//   __syncthreads -> cross-thread visibility of slab ks AND pbuf compute done
//   prefetch slab ks+2 into pbuf, commit
//   compute slab ks from buf
// During compute, slabs ks+1 and ks+2 are in flight (2-deep prefetch).
// grid (2048/64, 256/64) = (32, 4) = 128 CTAs.
__global__ __launch_bounds__(256) void step_kernel(int parity, int t) {
    const float*         __restrict__ rin_f   = g_r[parity];
    float*               __restrict__ rout_f  = g_r[parity ^ 1];
    const __nv_bfloat16* __restrict__ rhi_in  = g_rhi[parity];
    const __nv_bfloat16* __restrict__ rlo_in  = g_rlo[parity];
    __nv_bfloat16*       __restrict__ rhi_out = g_rhi[parity ^ 1];
    __nv_bfloat16*       __restrict__ rlo_out = g_rlo[parity ^ 1];

    extern __shared__ __align__(16) unsigned char smraw[];
    const uint32_t S0 = (uint32_t)__cvta_generic_to_shared(smraw);
    const uint32_t A_HI = S0;
    const uint32_t A_LO = S0 + 1 * NSTG * STAGE_BYTES;
    const uint32_t B_HI = S0 + 2 * NSTG * STAGE_BYTES;
    const uint32_t B_LO = S0 + 3 * NSTG * STAGE_BYTES;

    int tid = threadIdx.x;
    int lane = tid & 31, warp = tid >> 5;
    int n0 = blockIdx.x * 64;
    int m0 = blockIdx.y * 64;
    int wm = (warp >> 2) << 5;     // 0 / 32
    int wn = (warp & 3) << 4;      // 0..48
    int g = lane >> 2, tg = lane & 3;

    // ---- cp.async mapping: 256 threads cover 64x64 bf16 tile in 2 chunks
    int cr = tid >> 3;
    int cc = (tid & 7) << 3;
    uint32_t dOff0 = (uint32_t)cr * PITCHB + (cc << 1);
    uint32_t dOff1 = (uint32_t)(cr + 32) * PITCHB + (cc << 1);
    const __nv_bfloat16* aHiS0 = rhi_in + (size_t)(m0 + cr) * NTOT + cc;
    const __nv_bfloat16* aHiS1 = rhi_in + (size_t)(m0 + cr + 32) * NTOT + cc;
    const __nv_bfloat16* aLoS0 = rlo_in + (size_t)(m0 + cr) * NTOT + cc;
    const __nv_bfloat16* aLoS1 = rlo_in + (size_t)(m0 + cr + 32) * NTOT + cc;
    const __nv_bfloat16* bHiS0 = g_Whi + (size_t)(n0 + cr) * NTOT + cc;
    const __nv_bfloat16* bHiS1 = g_Whi + (size_t)(n0 + cr + 32) * NTOT + cc;
    const __nv_bfloat16* bLoS0 = g_Wlo + (size_t)(n0 + cr) * NTOT + cc;
    const __nv_bfloat16* bLoS1 = g_Wlo + (size_t)(n0 + cr + 32) * NTOT + cc;

    // ---- ldmatrix per-lane offsets (layout proven)
    int aRow = (lane & 7) + (((lane >> 3) & 1) << 3);
    int aCol = ((lane >> 4) << 3);
    int bRow = (lane & 7) + ((lane >> 4) << 3);
    int bCol = (((lane >> 3) & 1) << 3);

    uint32_t aHiAddr0 = A_HI + (uint32_t)(wm + aRow) * PITCHB + (aCol << 1);
    uint32_t aHiAddr1 = A_HI + (uint32_t)(wm + 16 + aRow) * PITCHB + (aCol << 1);
    uint32_t aLoAddr0 = A_LO + (uint32_t)(wm + aRow) * PITCHB + (aCol << 1);
    uint32_t aLoAddr1 = A_LO + (uint32_t)(wm + 16 + aRow) * PITCHB + (aCol << 1);
    uint32_t bHiAddr  = B_HI + (uint32_t)(wn + bRow) * PITCHB + (bCol << 1);
    uint32_t bLoAddr  = B_LO + (uint32_t)(wn + bRow) * PITCHB + (bCol << 1);

    float acc[2][2][4];
#pragma unroll
    for (int mt = 0; mt < 2; mt++)
#pragma unroll
        for (int nt = 0; nt < 2; nt++)
#pragma unroll
            for (int q = 0; q < 4; q++) acc[mt][nt][q] = 0.f;

    // prologue: stage 0 (slab 0) and stage 1 (slab 1)
#pragma unroll
    for (int s = 0; s < 2; s++) {
        int k0 = s * KS;
        uint32_t so = (uint32_t)s * STAGE_BYTES;
        cpa16(A_HI + so + dOff0, aHiS0 + k0);
        cpa16(A_HI + so + dOff1, aHiS1 + k0);
        cpa16(A_LO + so + dOff0, aLoS0 + k0);
        cpa16(A_LO + so + dOff1, aLoS1 + k0);
        cpa16(B_HI + so + dOff0, bHiS0 + k0);
        cpa16(B_HI + so + dOff1, bHiS1 + k0);
        cpa16(B_LO + so + dOff0, bLoS0 + k0);
        cpa16(B_LO + so + dOff1, bLoS1 + k0);
        cpa_commit();
    }

    int buf = 0;        // ks % 3
    int pbuf = 2;       // (ks+2) % 3
#pragma unroll 1
    for (int ks = 0; ks < NSLAB; ks++) {
        uint32_t so = (uint32_t)buf * STAGE_BYTES;

        cpa_wait<1>();       // slab ks copies complete (this thread); slab ks+1 may be in flight
        __syncthreads();     // cross-thread visibility of slab ks + all warps done with pbuf

        if (ks + 2 < NSLAB) {
            int k2 = (ks + 2) * KS;
            uint32_t po = (uint32_t)pbuf * STAGE_BYTES;
            cpa16(A_HI + po + dOff0, aHiS0 + k2);
            cpa16(A_HI + po + dOff1, aHiS1 + k2);
            cpa16(A_LO + po + dOff0, aLoS0 + k2);
            cpa16(A_LO + po + dOff1, aLoS1 + k2);
            cpa16(B_HI + po + dOff0, bHiS0 + k2);
            cpa16(B_HI + po + dOff1, bHiS1 + k2);
            cpa16(B_LO + po + dOff0, bLoS0 + k2);
            cpa16(B_LO + po + dOff1, bLoS1 + k2);
        }
        cpa_commit();        // possibly empty group — keeps group counting uniform

#pragma unroll
        for (int kb = 0; kb < KS; kb += 16) {
            uint32_t ko = (uint32_t)kb << 1;   // bytes
            uint32_t ah[2][4], al[2][4], bh[4], bl[4];
            ldsm4(ah[0], aHiAddr0 + so + ko);
            ldsm4(ah[1], aHiAddr1 + so + ko);
            ldsm4(bh,    bHiAddr  + so + ko);
            ldsm4(al[0], aLoAddr0 + so + ko);
            ldsm4(al[1], aLoAddr1 + so + ko);
            ldsm4(bl,    bLoAddr  + so + ko);
#pragma unroll
            for (int mt = 0; mt < 2; mt++)
#pragma unroll
                for (int nt = 0; nt < 2; nt++) mma_bf16(acc[mt][nt], ah[mt], &bh[nt << 1]);
#pragma unroll
            for (int mt = 0; mt < 2; mt++)
#pragma unroll
                for (int nt = 0; nt < 2; nt++) mma_bf16(acc[mt][nt], ah[mt], &bl[nt << 1]);
#pragma unroll
            for (int mt = 0; mt < 2; mt++)
#pragma unroll
                for (int nt = 0; nt < 2; nt++) mma_bf16(acc[mt][nt], al[mt], &bh[nt << 1]);
        }

        buf = (buf == 2) ? 0 : buf + 1;
        pbuf = (pbuf == 2) ? 0 : pbuf + 1;
    }

    // epilogue
#pragma unroll
    for (int mt = 0; mt < 2; mt++) {
#pragma unroll
        for (int nt = 0; nt < 2; nt++) {
            int colb = n0 + wn + (nt << 3) + (tg << 1);
            float rate = (colb < NE) ? 0.05f : 0.1f;
#pragma unroll
            for (int h = 0; h < 2; h++) {
                int row = m0 + wm + (mt << 4) + g + (h << 3);
                size_t idx = (size_t)row * NTOT + colb;
                float2 iff = *(const float2*)&g_Iff[idx];
                float2 ro  = *(const float2*)&rin_f[idx];
                float I0 = acc[mt][nt][h * 2 + 0] + iff.x;
                float I1 = acc[mt][nt][h * 2 + 1] + iff.y;
                float rl0 = fmaxf(I0, 0.f), rl1 = fmaxf(I1, 0.f);
                float f0 = 0.04f * rl0 * rl0, f1 = 0.04f * rl1 * rl1;
                float rn0 = fmaf(rate, f0 - ro.x, ro.x);
                float rn1 = fmaf(rate, f1 - ro.y, ro.y);
                float2 rn2; rn2.x = rn0; rn2.y = rn1;
                *(float2*)&rout_f[idx] = rn2;
                __nv_bfloat16 h0 = __float2bfloat16_rn(rn0);
                __nv_bfloat16 h1 = __float2bfloat16_rn(rn1);
                __nv_bfloat16 l0 = __float2bfloat16_rn(rn0 - __bfloat162float(h0));
                __nv_bfloat16 l1 = __float2bfloat16_rn(rn1 - __bfloat162float(h1));
                uint32_t hp = (uint32_t)*(uint16_t*)&h0 | ((uint32_t)*(uint16_t*)&h1 << 16);
                uint32_t lp = (uint32_t)*(uint16_t*)&l0 | ((uint32_t)*(uint16_t*)&l1 << 16);
                *(uint32_t*)&rhi_out[idx] = hp;
                *(uint32_t*)&rlo_out[idx] = lp;
                if (t >= STEPS - LASTN) {
                    float2 a = *(float2*)&g_acc[idx];
                    a.x += rn0; a.y += rn1;
                    *(float2*)&g_acc[idx] = a;
                }
            }
        }
    }
}

// ---------------- finalize ----------------
__global__ void fin_kernel(float* __restrict__ out) {
    int i = blockIdx.x * blockDim.x + threadIdx.x;
    if (i < BB * NTOT) {
        int b = i >> 11;
        int j = i & 2047;
        float v = g_acc[i] * (1.0f / (float)LASTN);
        if (j < NE) out[b * NE + j] = v;
        else        out[BB * NE + b * NE + (j - NE)] = v;
    }
}

// ---------------- launch ----------------
extern "C" void kernel_launch(void* const* d_in, const int* in_sizes, int n_in,
                              void* d_out, int out_size) {
    const float* x    = (const float*)d_in[0];
    const float* WEE  = (const float*)d_in[1];
    const float* WEI  = (const float*)d_in[2];
    const float* WIE  = (const float*)d_in[3];
    const float* WII  = (const float*)d_in[4];
    const float* WffE = (const float*)d_in[5];
    const float* WffI = (const float*)d_in[6];
    float* out = (float*)d_out;

    cudaFuncSetAttribute(step_kernel, cudaFuncAttributeMaxDynamicSharedMemorySize, SMEM_TOTAL);

    prep_w_kernel<<<NTOT, 256>>>(WEE, WEI, WIE, WII);
    iff_kernel<<<dim3(NTOT / 256, BB / 16), 256>>>(x, WffE, WffI);
    zero_kernel<<<512, 512>>>();

    for (int t = 0; t < STEPS; t++) {
        step_kernel<<<dim3(NTOT / 64, BB / 64), 256, SMEM_TOTAL>>>(t & 1, t);
    }

    fin_kernel<<<(BB * NTOT + 511) / 512, 512>>>(out);
}

// round 17
// speedup vs baseline: 1.0360x; 1.0360x over previous
#include <cuda_runtime.h>
#include <cuda_bf16.h>
#include <cstdint>

#define BB    256
#define NE    1024
#define NTOT  2048
#define DD    256
#define STEPS 200
#define LASTN 50

// step kernel geometry
#define KS     64            // K-slab
#define NSLAB  (NTOT / KS)   // 32
#define NSTG   3             // pipeline stages
#define PITCHB 144           // bytes per smem row (64 bf16 = 128B + 16B pad)
#define STAGE_BYTES (64 * PITCHB)                   // 9216B per matrix-stage
#define SMEM_TOTAL  (4 * NSTG * STAGE_BYTES)        // 110592B

// ---------------- device scratch ----------------
__device__ __nv_bfloat16 g_Whi[NTOT * NTOT];
__device__ __nv_bfloat16 g_Wlo[NTOT * NTOT];
__device__ float g_Iff[BB * NTOT];
__device__ float g_r[2][BB * NTOT];
__device__ __nv_bfloat16 g_rhi[2][BB * NTOT];
__device__ __nv_bfloat16 g_rlo[2][BB * NTOT];
__device__ float g_acc[BB * NTOT];

// ---------------- weight prep (proven) ----------------
__global__ void prep_w_kernel(const float* __restrict__ WEE,
                              const float* __restrict__ WEI,
                              const float* __restrict__ WIE,
                              const float* __restrict__ WII) {
    __shared__ float red[256];
    int j = blockIdx.x;
    int tid = threadIdx.x;
    bool isE = (j < NE);
    const float* rawA;
    const float* rawB;
    float SA, SB;
    if (isE) {
        rawA = WEE + (size_t)j * NE;  SA = 3.75f;
        rawB = WEI + (size_t)j * NE;  SB = 1.86f;
    } else {
        int j2 = j - NE;
        rawA = WIE + (size_t)j2 * NE; SA = 3.13f;
        rawB = WII + (size_t)j2 * NE; SB = 1.11f - 0.02f;
    }
    float sA = 0.f, sB = 0.f;
    for (int k = tid; k < NE; k += 256) { sA += rawA[k]; sB += rawB[k]; }
    red[tid] = sA; __syncthreads();
    for (int s = 128; s > 0; s >>= 1) { if (tid < s) red[tid] += red[tid + s]; __syncthreads(); }
    float sumA = red[0]; __syncthreads();
    red[tid] = sB; __syncthreads();
    for (int s = 128; s > 0; s >>= 1) { if (tid < s) red[tid] += red[tid + s]; __syncthreads(); }
    float sumB = red[0];

    float gA = SA / (sumA + 1e-12f);
    float gB = SB / (sumB + 1e-12f);

    for (int k = tid; k < NE; k += 256) {
        float a = rawA[k];
        if (isE) a = fminf(a, 0.15f);
        a *= gA;
        __nv_bfloat16 ha = __float2bfloat16_rn(a);
        g_Whi[j * NTOT + k] = ha;
        g_Wlo[j * NTOT + k] = __float2bfloat16_rn(a - __bfloat162float(ha));

        float b = rawB[k];
        if (isE) b = fmaxf(b, 0.0005f);
        b = -b * gB;
        __nv_bfloat16 hb = __float2bfloat16_rn(b);
        g_Whi[j * NTOT + NE + k] = hb;
        g_Wlo[j * NTOT + NE + k] = __float2bfloat16_rn(b - __bfloat162float(hb));
    }
}

// ---------------- feed-forward currents ----------------
__global__ void iff_kernel(const float* __restrict__ x,
                           const float* __restrict__ WffE,
                           const float* __restrict__ WffI) {
    __shared__ float sx[16][DD];
    int tid = threadIdx.x;
    int jblk = blockIdx.x * 256;
    int bblk = blockIdx.y * 16;
    for (int i = 0; i < 16; i++) sx[i][tid] = x[(bblk + i) * DD + tid];
    __syncthreads();
    int j = jblk + tid;
    const float* wr = (j < NE) ? (WffE + (size_t)j * DD) : (WffI + (size_t)(j - NE) * DD);
    float acc[16];
#pragma unroll
    for (int b = 0; b < 16; b++) acc[b] = 0.f;
    for (int d = 0; d < DD; d++) {
        float wv = __ldg(wr + d);
#pragma unroll
        for (int b = 0; b < 16; b++) acc[b] += sx[b][d] * wv;
    }
    for (int b = 0; b < 16; b++) g_Iff[(bblk + b) * NTOT + j] = acc[b];
}

// ---------------- zero init ----------------
__global__ void zero_kernel() {
    int i = blockIdx.x * blockDim.x + threadIdx.x;
    int stride = gridDim.x * blockDim.x;
    const __nv_bfloat16 z16 = __float2bfloat16_rn(0.f);
    for (int k = i; k < BB * NTOT; k += stride) {
        g_r[0][k] = 0.f;  g_r[1][k] = 0.f;
        g_rhi[0][k] = z16; g_rhi[1][k] = z16;
        g_rlo[0][k] = z16; g_rlo[1][k] = z16;
        g_acc[k] = 0.f;
    }
}

// ---------------- helpers ----------------
__device__ __forceinline__ void mma_bf16(float* c, const uint32_t* a, const uint32_t* b) {
    asm volatile(
        "mma.sync.aligned.m16n8k16.row.col.f32.bf16.bf16.f32 "
        "{%0,%1,%2,%3}, {%4,%5,%6,%7}, {%8,%9}, {%0,%1,%2,%3};\n"
        : "+f"(c[0]), "+f"(c[1]), "+f"(c[2]), "+f"(c[3])
        : "r"(a[0]), "r"(a[1]), "r"(a[2]), "r"(a[3]), "r"(b[0]), "r"(b[1]));
}

__device__ __forceinline__ void ldsm4(uint32_t* r, uint32_t addr) {
    asm volatile("ldmatrix.sync.aligned.m8n8.x4.shared.b16 {%0,%1,%2,%3}, [%4];\n"
                 : "=r"(r[0]), "=r"(r[1]), "=r"(r[2]), "=r"(r[3]) : "r"(addr));
}

__device__ __forceinline__ void cpa16(uint32_t saddr, const void* gaddr) {
    asm volatile("cp.async.cg.shared.global [%0], [%1], 16;\n" :: "r"(saddr), "l"(gaddr));
}
__device__ __forceinline__ void cpa_commit() {
    asm volatile("cp.async.commit_group;\n" ::: "memory");
}
template <int N>
__device__ __forceinline__ void cpa_wait() {
    asm volatile("cp.async.wait_group %0;\n" :: "n"(N) : "memory");
}

// ---------------- one dynamics step ----------------
// CTA tile 64(M) x 64(N), 256 threads = 8 warps (2M x 4N), warp tile 32x16.
// K-slab 64, 3-stage cp.async pipeline (race-free order proven in R15).
// KEY CHANGE vs R15: 3-way accumulator split by product (hh/hl/lh) to cut the
// per-accumulator HMMA RAW chain from 384 to 128 links (12 independent chains
// per warp instead of 4). Summed in the epilogue.
// grid (2048/64, 256/64) = (32, 4) = 128 CTAs.
__global__ __launch_bounds__(256) void step_kernel(int parity, int t) {
    const float*         __restrict__ rin_f   = g_r[parity];
    float*               __restrict__ rout_f  = g_r[parity ^ 1];
    const __nv_bfloat16* __restrict__ rhi_in  = g_rhi[parity];
    const __nv_bfloat16* __restrict__ rlo_in  = g_rlo[parity];
    __nv_bfloat16*       __restrict__ rhi_out = g_rhi[parity ^ 1];
    __nv_bfloat16*       __restrict__ rlo_out = g_rlo[parity ^ 1];

    extern __shared__ __align__(16) unsigned char smraw[];
    const uint32_t S0 = (uint32_t)__cvta_generic_to_shared(smraw);
    const uint32_t A_HI = S0;
    const uint32_t A_LO = S0 + 1 * NSTG * STAGE_BYTES;
    const uint32_t B_HI = S0 + 2 * NSTG * STAGE_BYTES;
    const uint32_t B_LO = S0 + 3 * NSTG * STAGE_BYTES;

    int tid = threadIdx.x;
    int lane = tid & 31, warp = tid >> 5;
    int n0 = blockIdx.x * 64;
    int m0 = blockIdx.y * 64;
    int wm = (warp >> 2) << 5;     // 0 / 32
    int wn = (warp & 3) << 4;      // 0..48
    int g = lane >> 2, tg = lane & 3;

    // ---- cp.async mapping: 256 threads cover 64x64 bf16 tile in 2 chunks
    int cr = tid >> 3;
    int cc = (tid & 7) << 3;
    uint32_t dOff0 = (uint32_t)cr * PITCHB + (cc << 1);
    uint32_t dOff1 = (uint32_t)(cr + 32) * PITCHB + (cc << 1);
    const __nv_bfloat16* aHiS0 = rhi_in + (size_t)(m0 + cr) * NTOT + cc;
    const __nv_bfloat16* aHiS1 = rhi_in + (size_t)(m0 + cr + 32) * NTOT + cc;
    const __nv_bfloat16* aLoS0 = rlo_in + (size_t)(m0 + cr) * NTOT + cc;
    const __nv_bfloat16* aLoS1 = rlo_in + (size_t)(m0 + cr + 32) * NTOT + cc;
    const __nv_bfloat16* bHiS0 = g_Whi + (size_t)(n0 + cr) * NTOT + cc;
    const __nv_bfloat16* bHiS1 = g_Whi + (size_t)(n0 + cr + 32) * NTOT + cc;
    const __nv_bfloat16* bLoS0 = g_Wlo + (size_t)(n0 + cr) * NTOT + cc;
    const __nv_bfloat16* bLoS1 = g_Wlo + (size_t)(n0 + cr + 32) * NTOT + cc;

    // ---- ldmatrix per-lane offsets (layout proven)
    int aRow = (lane & 7) + (((lane >> 3) & 1) << 3);
    int aCol = ((lane >> 4) << 3);
    int bRow = (lane & 7) + ((lane >> 4) << 3);
    int bCol = (((lane >> 3) & 1) << 3);

    uint32_t aHiAddr0 = A_HI + (uint32_t)(wm + aRow) * PITCHB + (aCol << 1);
    uint32_t aHiAddr1 = A_HI + (uint32_t)(wm + 16 + aRow) * PITCHB + (aCol << 1);
    uint32_t aLoAddr0 = A_LO + (uint32_t)(wm + aRow) * PITCHB + (aCol << 1);
    uint32_t aLoAddr1 = A_LO + (uint32_t)(wm + 16 + aRow) * PITCHB + (aCol << 1);
    uint32_t bHiAddr  = B_HI + (uint32_t)(wn + bRow) * PITCHB + (bCol << 1);
    uint32_t bLoAddr  = B_LO + (uint32_t)(wn + bRow) * PITCHB + (bCol << 1);

    // 3-way split accumulators: accA = hi*hi, accB = hi*lo, accC = lo*hi
    float accA[2][2][4], accB[2][2][4], accC[2][2][4];
#pragma unroll
    for (int mt = 0; mt < 2; mt++)
#pragma unroll
        for (int nt = 0; nt < 2; nt++)
#pragma unroll
            for (int q = 0; q < 4; q++) {
                accA[mt][nt][q] = 0.f;
                accB[mt][nt][q] = 0.f;
                accC[mt][nt][q] = 0.f;
            }

    // prologue: stage 0 (slab 0) and stage 1 (slab 1)
#pragma unroll
    for (int s = 0; s < 2; s++) {
        int k0 = s * KS;
        uint32_t so = (uint32_t)s * STAGE_BYTES;
        cpa16(A_HI + so + dOff0, aHiS0 + k0);
        cpa16(A_HI + so + dOff1, aHiS1 + k0);
        cpa16(A_LO + so + dOff0, aLoS0 + k0);
        cpa16(A_LO + so + dOff1, aLoS1 + k0);
        cpa16(B_HI + so + dOff0, bHiS0 + k0);
        cpa16(B_HI + so + dOff1, bHiS1 + k0);
        cpa16(B_LO + so + dOff0, bLoS0 + k0);
        cpa16(B_LO + so + dOff1, bLoS1 + k0);
        cpa_commit();
    }

    int buf = 0;        // ks % 3
    int pbuf = 2;       // (ks+2) % 3
#pragma unroll 1
    for (int ks = 0; ks < NSLAB; ks++) {
        uint32_t so = (uint32_t)buf * STAGE_BYTES;

        cpa_wait<1>();       // slab ks copies complete (this thread)
        __syncthreads();     // cross-thread visibility of slab ks + pbuf compute done

        if (ks + 2 < NSLAB) {
            int k2 = (ks + 2) * KS;
            uint32_t po = (uint32_t)pbuf * STAGE_BYTES;
            cpa16(A_HI + po + dOff0, aHiS0 + k2);
            cpa16(A_HI + po + dOff1, aHiS1 + k2);
            cpa16(A_LO + po + dOff0, aLoS0 + k2);
            cpa16(A_LO + po + dOff1, aLoS1 + k2);
            cpa16(B_HI + po + dOff0, bHiS0 + k2);
            cpa16(B_HI + po + dOff1, bHiS1 + k2);
            cpa16(B_LO + po + dOff0, bLoS0 + k2);
            cpa16(B_LO + po + dOff1, bLoS1 + k2);
        }
        cpa_commit();        // possibly empty — keeps group counting uniform

#pragma unroll
        for (int kb = 0; kb < KS; kb += 16) {
            uint32_t ko = (uint32_t)kb << 1;   // bytes
            uint32_t ah[2][4], al[2][4], bh[4], bl[4];
            ldsm4(ah[0], aHiAddr0 + so + ko);
            ldsm4(ah[1], aHiAddr1 + so + ko);
            ldsm4(bh,    bHiAddr  + so + ko);
            ldsm4(al[0], aLoAddr0 + so + ko);
            ldsm4(al[1], aLoAddr1 + so + ko);
            ldsm4(bl,    bLoAddr  + so + ko);
            // 12 independent accumulation chains (3 products x 4 tiles)
#pragma unroll
            for (int mt = 0; mt < 2; mt++)
#pragma unroll
                for (int nt = 0; nt < 2; nt++) mma_bf16(accA[mt][nt], ah[mt], &bh[nt << 1]);
#pragma unroll
            for (int mt = 0; mt < 2; mt++)
#pragma unroll
                for (int nt = 0; nt < 2; nt++) mma_bf16(accB[mt][nt], ah[mt], &bl[nt << 1]);
#pragma unroll
            for (int mt = 0; mt < 2; mt++)
#pragma unroll
                for (int nt = 0; nt < 2; nt++) mma_bf16(accC[mt][nt], al[mt], &bh[nt << 1]);
        }

        buf = (buf == 2) ? 0 : buf + 1;
        pbuf = (pbuf == 2) ? 0 : pbuf + 1;
    }

    // epilogue: combine split accumulators, then pointwise update
#pragma unroll
    for (int mt = 0; mt < 2; mt++) {
#pragma unroll
        for (int nt = 0; nt < 2; nt++) {
            int colb = n0 + wn + (nt << 3) + (tg << 1);
            float rate = (colb < NE) ? 0.05f : 0.1f;
#pragma unroll
            for (int h = 0; h < 2; h++) {
                int row = m0 + wm + (mt << 4) + g + (h << 3);
                size_t idx = (size_t)row * NTOT + colb;
                float2 iff = *(const float2*)&g_Iff[idx];
                float2 ro  = *(const float2*)&rin_f[idx];
                float s0 = accA[mt][nt][h * 2 + 0] + accB[mt][nt][h * 2 + 0]
                         + accC[mt][nt][h * 2 + 0];
                float s1 = accA[mt][nt][h * 2 + 1] + accB[mt][nt][h * 2 + 1]
                         + accC[mt][nt][h * 2 + 1];
                float I0 = s0 + iff.x;
                float I1 = s1 + iff.y;
                float rl0 = fmaxf(I0, 0.f), rl1 = fmaxf(I1, 0.f);
                float f0 = 0.04f * rl0 * rl0, f1 = 0.04f * rl1 * rl1;
                float rn0 = fmaf(rate, f0 - ro.x, ro.x);
                float rn1 = fmaf(rate, f1 - ro.y, ro.y);
                float2 rn2; rn2.x = rn0; rn2.y = rn1;
                *(float2*)&rout_f[idx] = rn2;
                __nv_bfloat16 h0 = __float2bfloat16_rn(rn0);
                __nv_bfloat16 h1 = __float2bfloat16_rn(rn1);
                __nv_bfloat16 l0 = __float2bfloat16_rn(rn0 - __bfloat162float(h0));
                __nv_bfloat16 l1 = __float2bfloat16_rn(rn1 - __bfloat162float(h1));
                uint32_t hp = (uint32_t)*(uint16_t*)&h0 | ((uint32_t)*(uint16_t*)&h1 << 16);
                uint32_t lp = (uint32_t)*(uint16_t*)&l0 | ((uint32_t)*(uint16_t*)&l1 << 16);
                *(uint32_t*)&rhi_out[idx] = hp;
                *(uint32_t*)&rlo_out[idx] = lp;
                if (t >= STEPS - LASTN) {
                    float2 a = *(float2*)&g_acc[idx];
                    a.x += rn0; a.y += rn1;
                    *(float2*)&g_acc[idx] = a;
                }
            }
        }
    }
}

// ---------------- finalize ----------------
__global__ void fin_kernel(float* __restrict__ out) {
    int i = blockIdx.x * blockDim.x + threadIdx.x;
    if (i < BB * NTOT) {
        int b = i >> 11;
        int j = i & 2047;
        float v = g_acc[i] * (1.0f / (float)LASTN);
        if (j < NE) out[b * NE + j] = v;
        else        out[BB * NE + b * NE + (j - NE)] = v;
    }
}

// ---------------- launch ----------------
extern "C" void kernel_launch(void* const* d_in, const int* in_sizes, int n_in,
                              void* d_out, int out_size) {
    const float* x    = (const float*)d_in[0];
    const float* WEE  = (const float*)d_in[1];
    const float* WEI  = (const float*)d_in[2];
    const float* WIE  = (const float*)d_in[3];
    const float* WII  = (const float*)d_in[4];
    const float* WffE = (const float*)d_in[5];
    const float* WffI = (const float*)d_in[6];
    float* out = (float*)d_out;

    cudaFuncSetAttribute(step_kernel, cudaFuncAttributeMaxDynamicSharedMemorySize, SMEM_TOTAL);

    prep_w_kernel<<<NTOT, 256>>>(WEE, WEI, WIE, WII);
    iff_kernel<<<dim3(NTOT / 256, BB / 16), 256>>>(x, WffE, WffI);
    zero_kernel<<<512, 512>>>();

    for (int t = 0; t < STEPS; t++) {
        step_kernel<<<dim3(NTOT / 64, BB / 64), 256, SMEM_TOTAL>>>(t & 1, t);
    }

    fin_kernel<<<(BB * NTOT + 511) / 512, 512>>>(out);
}